// round 4
// baseline (speedup 1.0000x reference)
#include <cuda_runtime.h>
#include <math.h>
#include <stdint.h>

#define HDIM 128
#define NMAX 20001
#define EMAX 200000

static __device__ float g_Xn[(size_t)NMAX * HDIM * 9];
static __device__ float g_tr[(size_t)NMAX * HDIM];
static __device__ float g_a [(size_t)NMAX * 3 * HDIM];
static __device__ float g_s [(size_t)NMAX * 6 * HDIM];
static __device__ float g_tI[(size_t)NMAX * HDIM];
static __device__ float g_aL[(size_t)NMAX * 3 * HDIM];
static __device__ float g_sL[(size_t)NMAX * 6 * HDIM];
static __device__ float g_h1[(size_t)EMAX * 128];
static __device__ float g_h2[(size_t)EMAX * 256];
static __device__ float g_h3[(size_t)EMAX * 384];
static __device__ float g_msg[(size_t)9 * NMAX * HDIM];

__device__ __forceinline__ float silu_f(float x) {
    return x / (1.0f + __expf(-x));
}

// ---------------------------------------------------------------------------
// Kernel 1: normalize X, decompose into (trace, antisym(3), symtraceless(6))
// ---------------------------------------------------------------------------
__global__ void k_prep(const float* __restrict__ X, int NH,
                       float* __restrict__ Xn, float* __restrict__ tr,
                       float* __restrict__ a, float* __restrict__ s) {
    int idx = blockIdx.x * blockDim.x + threadIdx.x;
    if (idx >= NH) return;
    const float* xp = X + (size_t)idx * 9;
    float x[9];
    float tn = 0.f;
#pragma unroll
    for (int p = 0; p < 9; p++) { x[p] = xp[p]; tn += x[p] * x[p]; }
    float inv = 1.0f / (tn + 1.0f);
    float* xo = Xn + (size_t)idx * 9;
#pragma unroll
    for (int p = 0; p < 9; p++) { x[p] *= inv; xo[p] = x[p]; }
    float trm = (x[0] + x[4] + x[8]) * (1.0f / 3.0f);
    int n = idx >> 7, c = idx & 127;
    tr[idx] = trm;
    a[(size_t)(n * 3 + 0) * HDIM + c] = 0.5f * (x[1] - x[3]);
    a[(size_t)(n * 3 + 1) * HDIM + c] = 0.5f * (x[2] - x[6]);
    a[(size_t)(n * 3 + 2) * HDIM + c] = 0.5f * (x[5] - x[7]);
    s[(size_t)(n * 6 + 0) * HDIM + c] = x[0] - trm;
    s[(size_t)(n * 6 + 1) * HDIM + c] = 0.5f * (x[1] + x[3]);
    s[(size_t)(n * 6 + 2) * HDIM + c] = 0.5f * (x[2] + x[6]);
    s[(size_t)(n * 6 + 3) * HDIM + c] = x[4] - trm;
    s[(size_t)(n * 6 + 4) * HDIM + c] = 0.5f * (x[5] + x[7]);
    s[(size_t)(n * 6 + 5) * HDIM + c] = x[8] - trm;
}

// ---------------------------------------------------------------------------
// Generic fp32 GEMM: C[r, c] = act( sum_k A[r,k] * W[c,k] + bias[c] )
// A: [R, K] row-major, W: [Ncols, K] row-major. K % 16 == 0, Ncols % 128 == 0.
// Tile 64x128, 256 threads, 8x4 per thread.
// ---------------------------------------------------------------------------
template <bool ACT, bool BIAS>
__global__ void gemm_kernel(const float* __restrict__ A, const float* __restrict__ W,
                            const float* __restrict__ bias, float* __restrict__ C,
                            int R, int K, int Ncols) {
    __shared__ float As[16][64];
    __shared__ float Ws[16][128];
    const int tid = threadIdx.x;
    const int block_row = blockIdx.x * 64;
    const int block_col = blockIdx.y * 128;
    const int tcol = tid & 31;   // 0..31 -> cols tcol*4 .. +3
    const int trow = tid >> 5;   // 0..7  -> rows trow*8 .. +7

    float acc[8][4];
#pragma unroll
    for (int i = 0; i < 8; i++)
#pragma unroll
        for (int j = 0; j < 4; j++) acc[i][j] = 0.f;

    const int a_r = tid >> 2;           // 0..63
    const int a_k = (tid & 3) * 4;      // 0,4,8,12
    const int w_c = tid >> 1;           // 0..127
    const int w_k = (tid & 1) * 8;      // 0,8

    for (int k0 = 0; k0 < K; k0 += 16) {
        int gr = block_row + a_r;
        float4 av = make_float4(0.f, 0.f, 0.f, 0.f);
        if (gr < R)
            av = *reinterpret_cast<const float4*>(A + (size_t)gr * K + k0 + a_k);
        As[a_k + 0][a_r] = av.x;
        As[a_k + 1][a_r] = av.y;
        As[a_k + 2][a_r] = av.z;
        As[a_k + 3][a_r] = av.w;

        const float* wp = W + (size_t)(block_col + w_c) * K + k0 + w_k;
        float4 w0 = *reinterpret_cast<const float4*>(wp);
        float4 w1 = *reinterpret_cast<const float4*>(wp + 4);
        Ws[w_k + 0][w_c] = w0.x; Ws[w_k + 1][w_c] = w0.y;
        Ws[w_k + 2][w_c] = w0.z; Ws[w_k + 3][w_c] = w0.w;
        Ws[w_k + 4][w_c] = w1.x; Ws[w_k + 5][w_c] = w1.y;
        Ws[w_k + 6][w_c] = w1.z; Ws[w_k + 7][w_c] = w1.w;
        __syncthreads();

#pragma unroll
        for (int kk = 0; kk < 16; kk++) {
            float4 wv  = *reinterpret_cast<const float4*>(&Ws[kk][tcol * 4]);
            float4 av0 = *reinterpret_cast<const float4*>(&As[kk][trow * 8]);
            float4 av1 = *reinterpret_cast<const float4*>(&As[kk][trow * 8 + 4]);
            float ar[8] = {av0.x, av0.y, av0.z, av0.w, av1.x, av1.y, av1.z, av1.w};
            float wr[4] = {wv.x, wv.y, wv.z, wv.w};
#pragma unroll
            for (int i = 0; i < 8; i++)
#pragma unroll
                for (int j = 0; j < 4; j++) acc[i][j] += ar[i] * wr[j];
        }
        __syncthreads();
    }

    float4 bv = make_float4(0.f, 0.f, 0.f, 0.f);
    if (BIAS) bv = *reinterpret_cast<const float4*>(bias + block_col + tcol * 4);
#pragma unroll
    for (int i = 0; i < 8; i++) {
        int gr = block_row + trow * 8 + i;
        if (gr < R) {
            float4 o;
            o.x = acc[i][0] + bv.x;
            o.y = acc[i][1] + bv.y;
            o.z = acc[i][2] + bv.z;
            o.w = acc[i][3] + bv.w;
            if (ACT) { o.x = silu_f(o.x); o.y = silu_f(o.y); o.z = silu_f(o.z); o.w = silu_f(o.w); }
            *reinterpret_cast<float4*>(C + (size_t)gr * Ncols + block_col + tcol * 4) = o;
        }
    }
}

// ---------------------------------------------------------------------------
// zero msg buffer
// ---------------------------------------------------------------------------
__global__ void k_zero(float* __restrict__ p, size_t n) {
    size_t i = (size_t)blockIdx.x * blockDim.x + threadIdx.x;
    if (i < n) p[i] = 0.f;
}

// ---------------------------------------------------------------------------
// Message passing: per (edge, channel) -> 9 atomic adds into msg[9][N][128]
// ---------------------------------------------------------------------------
__global__ void k_mp(const int* __restrict__ eidx, const float* __restrict__ ew,
                     const float* __restrict__ h3,
                     const float* __restrict__ tI, const float* __restrict__ aL,
                     const float* __restrict__ sL, const float* __restrict__ b1,
                     float* __restrict__ msg, int E, int NH) {
    int e = blockIdx.x * 2 + (threadIdx.x >> 7);
    int c = threadIdx.x & 127;
    if (e >= E) return;
    int dst = eidx[e];
    int src = eidx[E + e];
    float w = ew[e];
    const float PI_OVER = 3.14159265358979323846f / 4.5f;
    float Cc = (w < 4.5f) ? 0.5f * (__cosf(w * PI_OVER) + 1.0f) : 0.0f;

    const float* hp = h3 + (size_t)e * 384 + c * 3;
    float f0 = hp[0] * Cc;
    float f1 = hp[1] * Cc;
    float f2 = hp[2] * Cc;

    float ti = tI[(size_t)src * HDIM + c];
    float a0 = aL[(size_t)(src * 3 + 0) * HDIM + c];
    float a1 = aL[(size_t)(src * 3 + 1) * HDIM + c];
    float a2 = aL[(size_t)(src * 3 + 2) * HDIM + c];
    float s0 = sL[(size_t)(src * 6 + 0) * HDIM + c];
    float s1 = sL[(size_t)(src * 6 + 1) * HDIM + c];
    float s2 = sL[(size_t)(src * 6 + 2) * HDIM + c];
    float s3 = sL[(size_t)(src * 6 + 3) * HDIM + c];
    float s4 = sL[(size_t)(src * 6 + 4) * HDIM + c];
    float s5 = sL[(size_t)(src * 6 + 5) * HDIM + c];
    float b0 = b1[c], bb = b1[128 + c], b2 = b1[256 + c];

    float m[9];
    m[0] = f0 * (ti + b0) + f1 * bb        + f2 * (s0 + b2);
    m[1] = f0 * b0        + f1 * (a0 + bb) + f2 * (s1 + b2);
    m[2] = f0 * b0        + f1 * (a1 + bb) + f2 * (s2 + b2);
    m[3] = f0 * b0        + f1 * (-a0 + bb)+ f2 * (s1 + b2);
    m[4] = f0 * (ti + b0) + f1 * bb        + f2 * (s3 + b2);
    m[5] = f0 * b0        + f1 * (a2 + bb) + f2 * (s4 + b2);
    m[6] = f0 * b0        + f1 * (-a1 + bb)+ f2 * (s2 + b2);
    m[7] = f0 * b0        + f1 * (-a2 + bb)+ f2 * (s4 + b2);
    m[8] = f0 * (ti + b0) + f1 * bb        + f2 * (s5 + b2);

    size_t base = (size_t)dst * HDIM + c;
#pragma unroll
    for (int p = 0; p < 9; p++)
        atomicAdd(&msg[(size_t)p * NH + base], m[p]);
}

// ---------------------------------------------------------------------------
// Combine: NF = msg@Y + Y@msg, normalize, decompose -> (tr, a, s) buffers
// ---------------------------------------------------------------------------
__global__ void k_combine(const float* __restrict__ b1,
                          const float* __restrict__ msg,
                          const float* __restrict__ tI, const float* __restrict__ aL,
                          const float* __restrict__ sL,
                          float* __restrict__ tr, float* __restrict__ a,
                          float* __restrict__ s, int NH) {
    int idx = blockIdx.x * blockDim.x + threadIdx.x;
    if (idx >= NH) return;
    int n = idx >> 7, c = idx & 127;

    float M[9];
#pragma unroll
    for (int p = 0; p < 9; p++) M[p] = msg[(size_t)p * NH + idx];

    float ti = tI[idx];
    float a0 = aL[(size_t)(n * 3 + 0) * HDIM + c];
    float a1 = aL[(size_t)(n * 3 + 1) * HDIM + c];
    float a2 = aL[(size_t)(n * 3 + 2) * HDIM + c];
    float s0 = sL[(size_t)(n * 6 + 0) * HDIM + c];
    float s1 = sL[(size_t)(n * 6 + 1) * HDIM + c];
    float s2 = sL[(size_t)(n * 6 + 2) * HDIM + c];
    float s3 = sL[(size_t)(n * 6 + 3) * HDIM + c];
    float s4 = sL[(size_t)(n * 6 + 4) * HDIM + c];
    float s5 = sL[(size_t)(n * 6 + 5) * HDIM + c];
    float bsum = b1[c] + b1[128 + c] + b1[256 + c];

    float Y[9] = {
        ti + s0 + bsum,  a0 + s1 + bsum,  a1 + s2 + bsum,
        -a0 + s1 + bsum, ti + s3 + bsum,  a2 + s4 + bsum,
        -a1 + s2 + bsum, -a2 + s4 + bsum, ti + s5 + bsum
    };

    float NF[9];
#pragma unroll
    for (int i = 0; i < 3; i++)
#pragma unroll
        for (int j = 0; j < 3; j++) {
            float acc = 0.f;
#pragma unroll
            for (int k = 0; k < 3; k++)
                acc += M[i * 3 + k] * Y[k * 3 + j] + Y[i * 3 + k] * M[k * 3 + j];
            NF[i * 3 + j] = acc;
        }

    float tn = 0.f;
#pragma unroll
    for (int p = 0; p < 9; p++) tn += NF[p] * NF[p];
    float inv = 1.0f / (tn + 1.0f);
    float trm = (NF[0] + NF[4] + NF[8]) * (1.0f / 3.0f);

    tr[idx] = trm * inv;
    a[(size_t)(n * 3 + 0) * HDIM + c] = 0.5f * (NF[1] - NF[3]) * inv;
    a[(size_t)(n * 3 + 1) * HDIM + c] = 0.5f * (NF[2] - NF[6]) * inv;
    a[(size_t)(n * 3 + 2) * HDIM + c] = 0.5f * (NF[5] - NF[7]) * inv;
    s[(size_t)(n * 6 + 0) * HDIM + c] = (NF[0] - trm) * inv;
    s[(size_t)(n * 6 + 1) * HDIM + c] = 0.5f * (NF[1] + NF[3]) * inv;
    s[(size_t)(n * 6 + 2) * HDIM + c] = 0.5f * (NF[2] + NF[6]) * inv;
    s[(size_t)(n * 6 + 3) * HDIM + c] = (NF[4] - trm) * inv;
    s[(size_t)(n * 6 + 4) * HDIM + c] = 0.5f * (NF[5] + NF[7]) * inv;
    s[(size_t)(n * 6 + 5) * HDIM + c] = (NF[8] - trm) * inv;
}

// ---------------------------------------------------------------------------
// Output: dX assembled from W3-linear parts; out = Xn + dX + dX@dX
// ---------------------------------------------------------------------------
__global__ void k_out(const float* __restrict__ b3, const float* __restrict__ Xn,
                      const float* __restrict__ tI, const float* __restrict__ aL,
                      const float* __restrict__ sL, float* __restrict__ out, int NH) {
    int idx = blockIdx.x * blockDim.x + threadIdx.x;
    if (idx >= NH) return;
    int n = idx >> 7, c = idx & 127;

    float ti = tI[idx];
    float a0 = aL[(size_t)(n * 3 + 0) * HDIM + c];
    float a1 = aL[(size_t)(n * 3 + 1) * HDIM + c];
    float a2 = aL[(size_t)(n * 3 + 2) * HDIM + c];
    float s0 = sL[(size_t)(n * 6 + 0) * HDIM + c];
    float s1 = sL[(size_t)(n * 6 + 1) * HDIM + c];
    float s2 = sL[(size_t)(n * 6 + 2) * HDIM + c];
    float s3 = sL[(size_t)(n * 6 + 3) * HDIM + c];
    float s4 = sL[(size_t)(n * 6 + 4) * HDIM + c];
    float s5 = sL[(size_t)(n * 6 + 5) * HDIM + c];
    float bs = b3[c] + b3[128 + c] + b3[256 + c];

    float D[9] = {
        ti + s0 + bs,  a0 + s1 + bs,  a1 + s2 + bs,
        -a0 + s1 + bs, ti + s3 + bs,  a2 + s4 + bs,
        -a1 + s2 + bs, -a2 + s4 + bs, ti + s5 + bs
    };

    const float* xp = Xn + (size_t)idx * 9;
    float* op = out + (size_t)idx * 9;
#pragma unroll
    for (int i = 0; i < 3; i++)
#pragma unroll
        for (int j = 0; j < 3; j++) {
            float acc = 0.f;
#pragma unroll
            for (int k = 0; k < 3; k++) acc += D[i * 3 + k] * D[k * 3 + j];
            op[i * 3 + j] = xp[i * 3 + j] + D[i * 3 + j] + acc;
        }
}

// ---------------------------------------------------------------------------
extern "C" void kernel_launch(void* const* d_in, const int* in_sizes, int n_in,
                              void* d_out, int out_size) {
    const float* X     = (const float*)d_in[0];
    const int*   eidx  = (const int*)  d_in[1];
    const float* ew    = (const float*)d_in[2];
    const float* eattr = (const float*)d_in[3];
    const float* W1    = (const float*)d_in[4];
    const float* b1    = (const float*)d_in[5];
    const float* W2a   = (const float*)d_in[6];
    const float* b2a   = (const float*)d_in[7];
    const float* W2b   = (const float*)d_in[8];
    const float* b2b   = (const float*)d_in[9];
    const float* W2c   = (const float*)d_in[10];
    const float* b2c   = (const float*)d_in[11];
    const float* W3    = (const float*)d_in[12];
    const float* b3    = (const float*)d_in[13];

    int N  = in_sizes[0] / (HDIM * 9);
    int E  = in_sizes[2];
    int NH = N * HDIM;

    float *Xn, *tr, *a, *s, *tI, *aL, *sL, *h1, *h2, *h3, *msg;
    cudaGetSymbolAddress((void**)&Xn,  g_Xn);
    cudaGetSymbolAddress((void**)&tr,  g_tr);
    cudaGetSymbolAddress((void**)&a,   g_a);
    cudaGetSymbolAddress((void**)&s,   g_s);
    cudaGetSymbolAddress((void**)&tI,  g_tI);
    cudaGetSymbolAddress((void**)&aL,  g_aL);
    cudaGetSymbolAddress((void**)&sL,  g_sL);
    cudaGetSymbolAddress((void**)&h1,  g_h1);
    cudaGetSymbolAddress((void**)&h2,  g_h2);
    cudaGetSymbolAddress((void**)&h3,  g_h3);
    cudaGetSymbolAddress((void**)&msg, g_msg);

    // 1. normalize + decompose
    k_prep<<<(NH + 255) / 256, 256>>>(X, NH, Xn, tr, a, s);

    // 2. node channel-linears with W1 (I/A/S parts)
    gemm_kernel<false, false><<<dim3((N     + 63) / 64, 1), 256>>>(tr, W1,                 nullptr, tI, N,     128, 128);
    gemm_kernel<false, false><<<dim3((3 * N + 63) / 64, 1), 256>>>(a,  W1 + 128 * 128,     nullptr, aL, 3 * N, 128, 128);
    gemm_kernel<false, false><<<dim3((6 * N + 63) / 64, 1), 256>>>(s,  W1 + 2 * 128 * 128, nullptr, sL, 6 * N, 128, 128);

    // 3. edge MLP (bias + silu fused)
    gemm_kernel<true, true><<<dim3((E + 63) / 64, 1), 256>>>(eattr, W2a, b2a, h1, E, 64,  128);
    gemm_kernel<true, true><<<dim3((E + 63) / 64, 2), 256>>>(h1,    W2b, b2b, h2, E, 128, 256);
    gemm_kernel<true, true><<<dim3((E + 63) / 64, 3), 256>>>(h2,    W2c, b2c, h3, E, 256, 384);

    // 4. message passing (atomic scatter)
    size_t msz = (size_t)9 * NH;
    k_zero<<<(int)((msz + 255) / 256), 256>>>(msg, msz);
    k_mp<<<(E + 1) / 2, 256>>>(eidx, ew, h3, tI, aL, sL, b1, msg, E, NH);

    // 5. combine: NF = msg@Y + Y@msg, decompose+normalize
    k_combine<<<(NH + 255) / 256, 256>>>(b1, msg, tI, aL, sL, tr, a, s, NH);

    // 6. node channel-linears with W3
    gemm_kernel<false, false><<<dim3((N     + 63) / 64, 1), 256>>>(tr, W3,                 nullptr, tI, N,     128, 128);
    gemm_kernel<false, false><<<dim3((3 * N + 63) / 64, 1), 256>>>(a,  W3 + 128 * 128,     nullptr, aL, 3 * N, 128, 128);
    gemm_kernel<false, false><<<dim3((6 * N + 63) / 64, 1), 256>>>(s,  W3 + 2 * 128 * 128, nullptr, sL, 6 * N, 128, 128);

    // 7. final assembly
    k_out<<<(NH + 255) / 256, 256>>>(b3, Xn, tI, aL, sL, (float*)d_out, NH);
}

// round 5
// speedup vs baseline: 1.0018x; 1.0018x over previous
#include <cuda_runtime.h>
#include <math.h>
#include <stdint.h>

#define HDIM 128
#define NMAX 20001
#define EMAX 200000

static __device__ float g_Xn[(size_t)NMAX * HDIM * 9];
static __device__ float g_tr[(size_t)NMAX * HDIM];
static __device__ float g_a [(size_t)NMAX * 3 * HDIM];
static __device__ float g_s [(size_t)NMAX * 6 * HDIM];
static __device__ float g_tI[(size_t)NMAX * HDIM];
static __device__ float g_aL[(size_t)NMAX * 3 * HDIM];
static __device__ float g_sL[(size_t)NMAX * 6 * HDIM];
static __device__ float g_h1[(size_t)EMAX * 128];
static __device__ float g_h2[(size_t)EMAX * 256];
static __device__ float g_h3[(size_t)EMAX * 384];
static __device__ float g_msg[(size_t)9 * NMAX * HDIM];

__device__ __forceinline__ float silu_f(float x) {
    return x / (1.0f + __expf(-x));
}

// ---------------------------------------------------------------------------
// Kernel 1: normalize X, decompose into (trace, antisym(3), symtraceless(6))
// ---------------------------------------------------------------------------
__global__ void k_prep(const float* __restrict__ X, int NH,
                       float* __restrict__ Xn, float* __restrict__ tr,
                       float* __restrict__ a, float* __restrict__ s) {
    int idx = blockIdx.x * blockDim.x + threadIdx.x;
    if (idx >= NH) return;
    const float* xp = X + (size_t)idx * 9;
    float x[9];
    float tn = 0.f;
#pragma unroll
    for (int p = 0; p < 9; p++) { x[p] = xp[p]; tn += x[p] * x[p]; }
    float inv = 1.0f / (tn + 1.0f);
    float* xo = Xn + (size_t)idx * 9;
#pragma unroll
    for (int p = 0; p < 9; p++) { x[p] *= inv; xo[p] = x[p]; }
    float trm = (x[0] + x[4] + x[8]) * (1.0f / 3.0f);
    int n = idx >> 7, c = idx & 127;
    tr[idx] = trm;
    a[(size_t)(n * 3 + 0) * HDIM + c] = 0.5f * (x[1] - x[3]);
    a[(size_t)(n * 3 + 1) * HDIM + c] = 0.5f * (x[2] - x[6]);
    a[(size_t)(n * 3 + 2) * HDIM + c] = 0.5f * (x[5] - x[7]);
    s[(size_t)(n * 6 + 0) * HDIM + c] = x[0] - trm;
    s[(size_t)(n * 6 + 1) * HDIM + c] = 0.5f * (x[1] + x[3]);
    s[(size_t)(n * 6 + 2) * HDIM + c] = 0.5f * (x[2] + x[6]);
    s[(size_t)(n * 6 + 3) * HDIM + c] = x[4] - trm;
    s[(size_t)(n * 6 + 4) * HDIM + c] = 0.5f * (x[5] + x[7]);
    s[(size_t)(n * 6 + 5) * HDIM + c] = x[8] - trm;
}

// ---------------------------------------------------------------------------
// Generic fp32 GEMM: C[r, c] = act( sum_k A[r,k] * W[c,k] + bias[c] )
// A: [R, K] row-major, W: [Ncols, K] row-major. K % 16 == 0, Ncols % 128 == 0.
// Tile 64x128, 256 threads, 8x4 per thread.
// ---------------------------------------------------------------------------
template <bool ACT, bool BIAS>
__global__ void gemm_kernel(const float* __restrict__ A, const float* __restrict__ W,
                            const float* __restrict__ bias, float* __restrict__ C,
                            int R, int K, int Ncols) {
    __shared__ float As[16][64];
    __shared__ float Ws[16][128];
    const int tid = threadIdx.x;
    const int block_row = blockIdx.x * 64;
    const int block_col = blockIdx.y * 128;
    const int tcol = tid & 31;   // 0..31 -> cols tcol*4 .. +3
    const int trow = tid >> 5;   // 0..7  -> rows trow*8 .. +7

    float acc[8][4];
#pragma unroll
    for (int i = 0; i < 8; i++)
#pragma unroll
        for (int j = 0; j < 4; j++) acc[i][j] = 0.f;

    const int a_r = tid >> 2;           // 0..63
    const int a_k = (tid & 3) * 4;      // 0,4,8,12
    const int w_c = tid >> 1;           // 0..127
    const int w_k = (tid & 1) * 8;      // 0,8

    for (int k0 = 0; k0 < K; k0 += 16) {
        int gr = block_row + a_r;
        float4 av = make_float4(0.f, 0.f, 0.f, 0.f);
        if (gr < R)
            av = *reinterpret_cast<const float4*>(A + (size_t)gr * K + k0 + a_k);
        As[a_k + 0][a_r] = av.x;
        As[a_k + 1][a_r] = av.y;
        As[a_k + 2][a_r] = av.z;
        As[a_k + 3][a_r] = av.w;

        const float* wp = W + (size_t)(block_col + w_c) * K + k0 + w_k;
        float4 w0 = *reinterpret_cast<const float4*>(wp);
        float4 w1 = *reinterpret_cast<const float4*>(wp + 4);
        Ws[w_k + 0][w_c] = w0.x; Ws[w_k + 1][w_c] = w0.y;
        Ws[w_k + 2][w_c] = w0.z; Ws[w_k + 3][w_c] = w0.w;
        Ws[w_k + 4][w_c] = w1.x; Ws[w_k + 5][w_c] = w1.y;
        Ws[w_k + 6][w_c] = w1.z; Ws[w_k + 7][w_c] = w1.w;
        __syncthreads();

#pragma unroll
        for (int kk = 0; kk < 16; kk++) {
            float4 wv  = *reinterpret_cast<const float4*>(&Ws[kk][tcol * 4]);
            float4 av0 = *reinterpret_cast<const float4*>(&As[kk][trow * 8]);
            float4 av1 = *reinterpret_cast<const float4*>(&As[kk][trow * 8 + 4]);
            float ar[8] = {av0.x, av0.y, av0.z, av0.w, av1.x, av1.y, av1.z, av1.w};
            float wr[4] = {wv.x, wv.y, wv.z, wv.w};
#pragma unroll
            for (int i = 0; i < 8; i++)
#pragma unroll
                for (int j = 0; j < 4; j++) acc[i][j] += ar[i] * wr[j];
        }
        __syncthreads();
    }

    float4 bv = make_float4(0.f, 0.f, 0.f, 0.f);
    if (BIAS) bv = *reinterpret_cast<const float4*>(bias + block_col + tcol * 4);
#pragma unroll
    for (int i = 0; i < 8; i++) {
        int gr = block_row + trow * 8 + i;
        if (gr < R) {
            float4 o;
            o.x = acc[i][0] + bv.x;
            o.y = acc[i][1] + bv.y;
            o.z = acc[i][2] + bv.z;
            o.w = acc[i][3] + bv.w;
            if (ACT) { o.x = silu_f(o.x); o.y = silu_f(o.y); o.z = silu_f(o.z); o.w = silu_f(o.w); }
            *reinterpret_cast<float4*>(C + (size_t)gr * Ncols + block_col + tcol * 4) = o;
        }
    }
}

// ---------------------------------------------------------------------------
// zero msg buffer
// ---------------------------------------------------------------------------
__global__ void k_zero(float* __restrict__ p, size_t n) {
    size_t i = (size_t)blockIdx.x * blockDim.x + threadIdx.x;
    if (i < n) p[i] = 0.f;
}

// ---------------------------------------------------------------------------
// Message passing: per (edge, channel) -> 9 atomic adds into msg[9][N][128]
// ---------------------------------------------------------------------------
__global__ void k_mp(const int* __restrict__ eidx, const float* __restrict__ ew,
                     const float* __restrict__ h3,
                     const float* __restrict__ tI, const float* __restrict__ aL,
                     const float* __restrict__ sL, const float* __restrict__ b1,
                     float* __restrict__ msg, int E, int NH) {
    int e = blockIdx.x * 2 + (threadIdx.x >> 7);
    int c = threadIdx.x & 127;
    if (e >= E) return;
    int dst = eidx[e];
    int src = eidx[E + e];
    float w = ew[e];
    const float PI_OVER = 3.14159265358979323846f / 4.5f;
    float Cc = (w < 4.5f) ? 0.5f * (__cosf(w * PI_OVER) + 1.0f) : 0.0f;

    const float* hp = h3 + (size_t)e * 384 + c * 3;
    float f0 = hp[0] * Cc;
    float f1 = hp[1] * Cc;
    float f2 = hp[2] * Cc;

    float ti = tI[(size_t)src * HDIM + c];
    float a0 = aL[(size_t)(src * 3 + 0) * HDIM + c];
    float a1 = aL[(size_t)(src * 3 + 1) * HDIM + c];
    float a2 = aL[(size_t)(src * 3 + 2) * HDIM + c];
    float s0 = sL[(size_t)(src * 6 + 0) * HDIM + c];
    float s1 = sL[(size_t)(src * 6 + 1) * HDIM + c];
    float s2 = sL[(size_t)(src * 6 + 2) * HDIM + c];
    float s3 = sL[(size_t)(src * 6 + 3) * HDIM + c];
    float s4 = sL[(size_t)(src * 6 + 4) * HDIM + c];
    float s5 = sL[(size_t)(src * 6 + 5) * HDIM + c];
    float b0 = b1[c], bb = b1[128 + c], b2 = b1[256 + c];

    float m[9];
    m[0] = f0 * (ti + b0) + f1 * bb        + f2 * (s0 + b2);
    m[1] = f0 * b0        + f1 * (a0 + bb) + f2 * (s1 + b2);
    m[2] = f0 * b0        + f1 * (a1 + bb) + f2 * (s2 + b2);
    m[3] = f0 * b0        + f1 * (-a0 + bb)+ f2 * (s1 + b2);
    m[4] = f0 * (ti + b0) + f1 * bb        + f2 * (s3 + b2);
    m[5] = f0 * b0        + f1 * (a2 + bb) + f2 * (s4 + b2);
    m[6] = f0 * b0        + f1 * (-a1 + bb)+ f2 * (s2 + b2);
    m[7] = f0 * b0        + f1 * (-a2 + bb)+ f2 * (s4 + b2);
    m[8] = f0 * (ti + b0) + f1 * bb        + f2 * (s5 + b2);

    size_t base = (size_t)dst * HDIM + c;
#pragma unroll
    for (int p = 0; p < 9; p++)
        atomicAdd(&msg[(size_t)p * NH + base], m[p]);
}

// ---------------------------------------------------------------------------
// Combine: NF = msg@Y + Y@msg, normalize, decompose -> (tr, a, s) buffers
// ---------------------------------------------------------------------------
__global__ void k_combine(const float* __restrict__ b1,
                          const float* __restrict__ msg,
                          const float* __restrict__ tI, const float* __restrict__ aL,
                          const float* __restrict__ sL,
                          float* __restrict__ tr, float* __restrict__ a,
                          float* __restrict__ s, int NH) {
    int idx = blockIdx.x * blockDim.x + threadIdx.x;
    if (idx >= NH) return;
    int n = idx >> 7, c = idx & 127;

    float M[9];
#pragma unroll
    for (int p = 0; p < 9; p++) M[p] = msg[(size_t)p * NH + idx];

    float ti = tI[idx];
    float a0 = aL[(size_t)(n * 3 + 0) * HDIM + c];
    float a1 = aL[(size_t)(n * 3 + 1) * HDIM + c];
    float a2 = aL[(size_t)(n * 3 + 2) * HDIM + c];
    float s0 = sL[(size_t)(n * 6 + 0) * HDIM + c];
    float s1 = sL[(size_t)(n * 6 + 1) * HDIM + c];
    float s2 = sL[(size_t)(n * 6 + 2) * HDIM + c];
    float s3 = sL[(size_t)(n * 6 + 3) * HDIM + c];
    float s4 = sL[(size_t)(n * 6 + 4) * HDIM + c];
    float s5 = sL[(size_t)(n * 6 + 5) * HDIM + c];
    float bsum = b1[c] + b1[128 + c] + b1[256 + c];

    float Y[9] = {
        ti + s0 + bsum,  a0 + s1 + bsum,  a1 + s2 + bsum,
        -a0 + s1 + bsum, ti + s3 + bsum,  a2 + s4 + bsum,
        -a1 + s2 + bsum, -a2 + s4 + bsum, ti + s5 + bsum
    };

    float NF[9];
#pragma unroll
    for (int i = 0; i < 3; i++)
#pragma unroll
        for (int j = 0; j < 3; j++) {
            float acc = 0.f;
#pragma unroll
            for (int k = 0; k < 3; k++)
                acc += M[i * 3 + k] * Y[k * 3 + j] + Y[i * 3 + k] * M[k * 3 + j];
            NF[i * 3 + j] = acc;
        }

    float tn = 0.f;
#pragma unroll
    for (int p = 0; p < 9; p++) tn += NF[p] * NF[p];
    float inv = 1.0f / (tn + 1.0f);
    float trm = (NF[0] + NF[4] + NF[8]) * (1.0f / 3.0f);

    tr[idx] = trm * inv;
    a[(size_t)(n * 3 + 0) * HDIM + c] = 0.5f * (NF[1] - NF[3]) * inv;
    a[(size_t)(n * 3 + 1) * HDIM + c] = 0.5f * (NF[2] - NF[6]) * inv;
    a[(size_t)(n * 3 + 2) * HDIM + c] = 0.5f * (NF[5] - NF[7]) * inv;
    s[(size_t)(n * 6 + 0) * HDIM + c] = (NF[0] - trm) * inv;
    s[(size_t)(n * 6 + 1) * HDIM + c] = 0.5f * (NF[1] + NF[3]) * inv;
    s[(size_t)(n * 6 + 2) * HDIM + c] = 0.5f * (NF[2] + NF[6]) * inv;
    s[(size_t)(n * 6 + 3) * HDIM + c] = (NF[4] - trm) * inv;
    s[(size_t)(n * 6 + 4) * HDIM + c] = 0.5f * (NF[5] + NF[7]) * inv;
    s[(size_t)(n * 6 + 5) * HDIM + c] = (NF[8] - trm) * inv;
}

// ---------------------------------------------------------------------------
// Output: dX assembled from W3-linear parts; out = Xn + dX + dX@dX
// ---------------------------------------------------------------------------
__global__ void k_out(const float* __restrict__ b3, const float* __restrict__ Xn,
                      const float* __restrict__ tI, const float* __restrict__ aL,
                      const float* __restrict__ sL, float* __restrict__ out, int NH) {
    int idx = blockIdx.x * blockDim.x + threadIdx.x;
    if (idx >= NH) return;
    int n = idx >> 7, c = idx & 127;

    float ti = tI[idx];
    float a0 = aL[(size_t)(n * 3 + 0) * HDIM + c];
    float a1 = aL[(size_t)(n * 3 + 1) * HDIM + c];
    float a2 = aL[(size_t)(n * 3 + 2) * HDIM + c];
    float s0 = sL[(size_t)(n * 6 + 0) * HDIM + c];
    float s1 = sL[(size_t)(n * 6 + 1) * HDIM + c];
    float s2 = sL[(size_t)(n * 6 + 2) * HDIM + c];
    float s3 = sL[(size_t)(n * 6 + 3) * HDIM + c];
    float s4 = sL[(size_t)(n * 6 + 4) * HDIM + c];
    float s5 = sL[(size_t)(n * 6 + 5) * HDIM + c];
    float bs = b3[c] + b3[128 + c] + b3[256 + c];

    float D[9] = {
        ti + s0 + bs,  a0 + s1 + bs,  a1 + s2 + bs,
        -a0 + s1 + bs, ti + s3 + bs,  a2 + s4 + bs,
        -a1 + s2 + bs, -a2 + s4 + bs, ti + s5 + bs
    };

    const float* xp = Xn + (size_t)idx * 9;
    float* op = out + (size_t)idx * 9;
#pragma unroll
    for (int i = 0; i < 3; i++)
#pragma unroll
        for (int j = 0; j < 3; j++) {
            float acc = 0.f;
#pragma unroll
            for (int k = 0; k < 3; k++) acc += D[i * 3 + k] * D[k * 3 + j];
            op[i * 3 + j] = xp[i * 3 + j] + D[i * 3 + j] + acc;
        }
}

// ---------------------------------------------------------------------------
extern "C" void kernel_launch(void* const* d_in, const int* in_sizes, int n_in,
                              void* d_out, int out_size) {
    const float* X     = (const float*)d_in[0];
    const int*   eidx  = (const int*)  d_in[1];
    const float* ew    = (const float*)d_in[2];
    const float* eattr = (const float*)d_in[3];
    const float* W1    = (const float*)d_in[4];
    const float* b1    = (const float*)d_in[5];
    const float* W2a   = (const float*)d_in[6];
    const float* b2a   = (const float*)d_in[7];
    const float* W2b   = (const float*)d_in[8];
    const float* b2b   = (const float*)d_in[9];
    const float* W2c   = (const float*)d_in[10];
    const float* b2c   = (const float*)d_in[11];
    const float* W3    = (const float*)d_in[12];
    const float* b3    = (const float*)d_in[13];

    int N  = in_sizes[0] / (HDIM * 9);
    int E  = in_sizes[2];
    int NH = N * HDIM;

    float *Xn, *tr, *a, *s, *tI, *aL, *sL, *h1, *h2, *h3, *msg;
    cudaGetSymbolAddress((void**)&Xn,  g_Xn);
    cudaGetSymbolAddress((void**)&tr,  g_tr);
    cudaGetSymbolAddress((void**)&a,   g_a);
    cudaGetSymbolAddress((void**)&s,   g_s);
    cudaGetSymbolAddress((void**)&tI,  g_tI);
    cudaGetSymbolAddress((void**)&aL,  g_aL);
    cudaGetSymbolAddress((void**)&sL,  g_sL);
    cudaGetSymbolAddress((void**)&h1,  g_h1);
    cudaGetSymbolAddress((void**)&h2,  g_h2);
    cudaGetSymbolAddress((void**)&h3,  g_h3);
    cudaGetSymbolAddress((void**)&msg, g_msg);

    // 1. normalize + decompose
    k_prep<<<(NH + 255) / 256, 256>>>(X, NH, Xn, tr, a, s);

    // 2. node channel-linears with W1 (I/A/S parts)
    gemm_kernel<false, false><<<dim3((N     + 63) / 64, 1), 256>>>(tr, W1,                 nullptr, tI, N,     128, 128);
    gemm_kernel<false, false><<<dim3((3 * N + 63) / 64, 1), 256>>>(a,  W1 + 128 * 128,     nullptr, aL, 3 * N, 128, 128);
    gemm_kernel<false, false><<<dim3((6 * N + 63) / 64, 1), 256>>>(s,  W1 + 2 * 128 * 128, nullptr, sL, 6 * N, 128, 128);

    // 3. edge MLP (bias + silu fused)
    gemm_kernel<true, true><<<dim3((E + 63) / 64, 1), 256>>>(eattr, W2a, b2a, h1, E, 64,  128);
    gemm_kernel<true, true><<<dim3((E + 63) / 64, 2), 256>>>(h1,    W2b, b2b, h2, E, 128, 256);
    gemm_kernel<true, true><<<dim3((E + 63) / 64, 3), 256>>>(h2,    W2c, b2c, h3, E, 256, 384);

    // 4. message passing (atomic scatter)
    size_t msz = (size_t)9 * NH;
    k_zero<<<(int)((msz + 255) / 256), 256>>>(msg, msz);
    k_mp<<<(E + 1) / 2, 256>>>(eidx, ew, h3, tI, aL, sL, b1, msg, E, NH);

    // 5. combine: NF = msg@Y + Y@msg, decompose+normalize
    k_combine<<<(NH + 255) / 256, 256>>>(b1, msg, tI, aL, sL, tr, a, s, NH);

    // 6. node channel-linears with W3
    gemm_kernel<false, false><<<dim3((N     + 63) / 64, 1), 256>>>(tr, W3,                 nullptr, tI, N,     128, 128);
    gemm_kernel<false, false><<<dim3((3 * N + 63) / 64, 1), 256>>>(a,  W3 + 128 * 128,     nullptr, aL, 3 * N, 128, 128);
    gemm_kernel<false, false><<<dim3((6 * N + 63) / 64, 1), 256>>>(s,  W3 + 2 * 128 * 128, nullptr, sL, 6 * N, 128, 128);

    // 7. final assembly
    k_out<<<(NH + 255) / 256, 256>>>(b3, Xn, tI, aL, sL, (float*)d_out, NH);
}